// round 13
// baseline (speedup 1.0000x reference)
#include <cuda_runtime.h>
#include <cuda_bf16.h>

#define N_ROWS 256
#define D_COLS 8192
#define LAMBDA 0.005f
#define SPLITS 48
#define NTILES 3              // symmetric 128x128 tile pairs: (0,0),(0,1),(1,1)
#define TILE_ELEMS 16384
#define BK 32                 // k per mainloop iter
#define LDB 40                // smem row stride in bf16 (80 B, odd granule count -> conflict-free)
#define SLOT_BUF 10240        // 128 * 80 B, one side one stage
#define NSTAGE 2
#define A_REGION (NSTAGE * SLOT_BUF)      // 20480
#define DYN_SMEM (2 * NSTAGE * SLOT_BUF)  // 40960
#define NBLK 296              // 2 CTAs per SM on 148 SMs
#define NTHR 512
#define NSTATS 256            // stats blocks (32 cols each)
#define NGRAM (2 * NTILES * SPLITS)       // 288
#define CROSS_TASKS 12288     // 3*TILE_ELEMS/4 float4 tasks
#define TPB_CROSS 42          // ceil(12288/296)

// ---- scratch ----
__device__ __align__(16) __nv_bfloat16 g_Zn[2][N_ROWS * D_COLS];      // normalized bf16, 8 MB
__device__ float g_diag[NSTATS];
__device__ __align__(16) float g_GP[2][SPLITS][NTILES * TILE_ELEMS];  // 18.9 MB partials
__device__ float g_red[NBLK];
__device__ unsigned g_bar_count;
__device__ unsigned g_bar_gen;
__device__ unsigned g_fin;

// ---------------------------------------------------------------------------
__device__ __forceinline__ void grid_sync() {
    __syncthreads();
    if (threadIdx.x == 0) {
        __threadfence();
        const unsigned gen = *(volatile unsigned*)&g_bar_gen;
        if (atomicAdd(&g_bar_count, 1u) == NBLK - 1) {
            g_bar_count = 0;
            __threadfence();
            *(volatile unsigned*)&g_bar_gen = gen + 1;
        } else {
            while (*(volatile unsigned*)&g_bar_gen == gen) {}
        }
        __threadfence();
    }
    __syncthreads();
}

__device__ __forceinline__ void mma_bf16(float* c, const unsigned* a, unsigned b0, unsigned b1) {
    asm volatile(
        "mma.sync.aligned.m16n8k16.row.col.f32.bf16.bf16.f32 "
        "{%0,%1,%2,%3}, {%4,%5,%6,%7}, {%8,%9}, {%0,%1,%2,%3};\n"
        : "+f"(c[0]), "+f"(c[1]), "+f"(c[2]), "+f"(c[3])
        : "r"(a[0]), "r"(a[1]), "r"(a[2]), "r"(a[3]), "r"(b0), "r"(b1));
}
__device__ __forceinline__ void ldm4(unsigned* r, unsigned addr) {
    asm volatile("ldmatrix.sync.aligned.m8n8.x4.shared.b16 {%0,%1,%2,%3}, [%4];\n"
        : "=r"(r[0]), "=r"(r[1]), "=r"(r[2]), "=r"(r[3]) : "r"(addr));
}
__device__ __forceinline__ void cp_async16(unsigned dst, const void* src) {
    asm volatile("cp.async.cg.shared.global [%0], [%1], 16;\n" :: "r"(dst), "l"(src));
}

__global__ __launch_bounds__(NTHR, 2)
void fused_kernel(const float* __restrict__ za, const float* __restrict__ zb,
                  float* __restrict__ out) {
    extern __shared__ __align__(16) unsigned char dyn[];
    __shared__ float s_red[NTHR];
    __shared__ unsigned s_last;

    const int bid = blockIdx.x;
    const int tid = threadIdx.x;

    // ========== Phase 0 (bid<256): stats + diag + normalize (32 cols/block) =
    if (bid < NSTATS) {
        float (*s_st)[32 * 5] = (float (*)[32 * 5])dyn;                   // [16][160] = 10240 B
        float* s_mu = (float*)(dyn + 10240);                               // [2][32]
        float* s_inv = (float*)(dyn + 10240 + 256);                        // [2][32]

        const int c = tid & 31;
        const int gq = tid >> 5;          // 0..15, 16 rows each
        const int col = bid * 32 + c;
        const float* __restrict__ pa = za + (size_t)(gq * 16) * D_COLS + col;
        const float* __restrict__ pb = zb + (size_t)(gq * 16) * D_COLS + col;
        float sa = 0.f, sb = 0.f, saa = 0.f, sbb = 0.f, sab = 0.f;
#pragma unroll
        for (int n = 0; n < 16; ++n) {
            float a = pa[n * D_COLS];
            float b = pb[n * D_COLS];
            sa += a; sb += b;
            saa += a * a; sbb += b * b; sab += a * b;
        }
        s_st[gq][c * 5 + 0] = sa;
        s_st[gq][c * 5 + 1] = sb;
        s_st[gq][c * 5 + 2] = saa;
        s_st[gq][c * 5 + 3] = sbb;
        s_st[gq][c * 5 + 4] = sab;
        __syncthreads();

        float term = 0.f;
        if (tid < 32) {
            float t0 = 0.f, t1 = 0.f, t2 = 0.f, t3 = 0.f, t4 = 0.f;
#pragma unroll
            for (int g = 0; g < 16; ++g) {
                t0 += s_st[g][tid * 5 + 0];
                t1 += s_st[g][tid * 5 + 1];
                t2 += s_st[g][tid * 5 + 2];
                t3 += s_st[g][tid * 5 + 3];
                t4 += s_st[g][tid * 5 + 4];
            }
            const float mua = t0 * (1.f / 256.f);
            const float mub = t1 * (1.f / 256.f);
            const float ia = rsqrtf((t2 - t0 * mua) * (1.f / 255.f));
            const float ib = rsqrtf((t3 - t1 * mub) * (1.f / 255.f));
            const float cdd = (t4 - 256.f * mua * mub) * ia * ib * (1.f / 256.f);
            term = (cdd - 1.f) * (cdd - 1.f) - LAMBDA * cdd * cdd;
            s_mu[tid] = mua; s_mu[32 + tid] = mub;
            s_inv[tid] = ia; s_inv[32 + tid] = ib;
        }
        s_red[tid] = term;
        __syncthreads();
#pragma unroll
        for (int off = 16; off > 0; off >>= 1) {   // data only in tids 0..31
            if (tid < off) s_red[tid] += s_red[tid + off];
            __syncthreads();
        }
        if (tid == 0) g_diag[bid] = s_red[0];

        // normalize slab -> bf16 (L2-hot re-read). 32 row-groups x 16 col-pairs.
        const int cp2 = tid & 15;
        const int rg = tid >> 4;              // 0..31, 8 rows each
        const int lc = cp2 * 2;
        const int gcol = bid * 32 + lc;
        const float ma0 = s_mu[lc],       ma1 = s_mu[lc + 1];
        const float wa0 = s_inv[lc],      wa1 = s_inv[lc + 1];
        const float mb0 = s_mu[32 + lc],  mb1 = s_mu[32 + lc + 1];
        const float wb0 = s_inv[32 + lc], wb1 = s_inv[32 + lc + 1];
        const float* __restrict__ qa = za + (size_t)(rg * 8) * D_COLS + gcol;
        const float* __restrict__ qb = zb + (size_t)(rg * 8) * D_COLS + gcol;
        __nv_bfloat16* __restrict__ oa = g_Zn[0] + (size_t)(rg * 8) * D_COLS + gcol;
        __nv_bfloat16* __restrict__ ob = g_Zn[1] + (size_t)(rg * 8) * D_COLS + gcol;
#pragma unroll
        for (int n = 0; n < 8; ++n) {
            float2 va = *(const float2*)&qa[n * D_COLS];
            float2 vb = *(const float2*)&qb[n * D_COLS];
            *(__nv_bfloat162*)&oa[n * D_COLS] =
                __floats2bfloat162_rn((va.x - ma0) * wa0, (va.y - ma1) * wa1);
            *(__nv_bfloat162*)&ob[n * D_COLS] =
                __floats2bfloat162_rn((vb.x - mb0) * wb0, (vb.y - mb1) * wb1);
        }
    }

    grid_sync();

    // ========== Phase 1 (bid<288): 2-stage pipelined tensor-core Gram =======
    // 16 warps, 4x4 warp grid, 32x32 warp tiles, BK=32, 1 barrier per iter.
    if (bid < NGRAM) {
        const int sel = bid / (NTILES * SPLITS);
        const int rem = bid % (NTILES * SPLITS);
        const int pair = rem / SPLITS;
        const int s = rem % SPLITS;
        const bool dup = (pair != 1);      // diagonal tile pairs: B tile == A tile

        const int m0 = (pair == 2) ? 128 : 0;
        const int n0 = (pair == 0) ? 0 : 128;
        // 256 k-chunks of 32: splits 0..15 get 6, 16..47 get 5 (16*6+32*5=256)
        const int ks = (s < 16) ? s * 6 : 96 + (s - 16) * 5;
        const int kn = (s < 16) ? 6 : 5;

        const __nv_bfloat16* __restrict__ gA = g_Zn[sel] + (size_t)m0 * D_COLS;
        const __nv_bfloat16* __restrict__ gB = g_Zn[sel] + (size_t)n0 * D_COLS;

        const int warp = tid >> 5;
        const int lane = tid & 31;
        const int wm = warp & 3;    // 4 m-strips of 32
        const int wn = warp >> 2;   // 4 n-strips of 32

        float acc[2][4][4];
#pragma unroll
        for (int i = 0; i < 2; ++i)
#pragma unroll
            for (int j = 0; j < 4; ++j)
#pragma unroll
                for (int k = 0; k < 4; ++k) acc[i][j][k] = 0.f;

        const unsigned sBase = (unsigned)__cvta_generic_to_shared(dyn);
        const unsigned bRegion = dup ? sBase : (sBase + (unsigned)A_REGION);
        const int laR = (lane & 7) + (lane & 8);
        const int laC = (lane >> 1) & 8;
        const int lbR = (lane & 7) + ((lane >> 1) & 8);
        const int lbC = (lane & 8);
        const unsigned aAddr = sBase + (unsigned)(((wm * 32 + laR) * LDB + laC) * 2);
        const unsigned bAddr = bRegion + (unsigned)(((wn * 32 + lbR) * LDB + lbC) * 2);

        // stage one 128x32 bf16 tile per side: 512 16B chunks -> 1 per thread
#define STAGE(slot, kidx)                                                         \
        {                                                                         \
            const int k0_ = (ks + (kidx)) * BK;                                   \
            const unsigned so_ = (unsigned)(slot) * SLOT_BUF;                     \
            const int r_ = tid >> 2;                                              \
            const int c_ = tid & 3;                                               \
            cp_async16(sBase + so_ + (unsigned)(r_ * 80 + c_ * 16),               \
                       gA + (size_t)r_ * D_COLS + k0_ + c_ * 8);                  \
            if (!dup)                                                             \
                cp_async16(sBase + (unsigned)A_REGION + so_ + (unsigned)(r_ * 80 + c_ * 16), \
                           gB + (size_t)r_ * D_COLS + k0_ + c_ * 8);              \
            asm volatile("cp.async.commit_group;\n");                             \
        }

        STAGE(0, 0);
        for (int it = 0; it < kn; ++it) {
            asm volatile("cp.async.wait_group 0;\n");   // slot it&1 data complete
            __syncthreads();                            // all warps past iter it-1 reads
            if (it + 1 < kn) STAGE((it + 1) & 1, it + 1);  // overlaps compute below

            const unsigned off = (unsigned)((it & 1) * SLOT_BUF);
#pragma unroll
            for (int kf = 0; kf < 2; ++kf) {
                unsigned A0[4], A1[4];
                ldm4(A0, aAddr + off + (unsigned)(kf * 32));
                ldm4(A1, aAddr + off + (unsigned)(16 * LDB * 2 + kf * 32));
#pragma unroll
                for (int fp = 0; fp < 2; ++fp) {
                    unsigned B[4];
                    ldm4(B, bAddr + off + (unsigned)(fp * 16 * LDB * 2 + kf * 32));
                    mma_bf16(acc[0][2 * fp],     A0, B[0], B[1]);
                    mma_bf16(acc[0][2 * fp + 1], A0, B[2], B[3]);
                    mma_bf16(acc[1][2 * fp],     A1, B[0], B[1]);
                    mma_bf16(acc[1][2 * fp + 1], A1, B[2], B[3]);
                }
            }
        }
#undef STAGE

        float* __restrict__ outp = &g_GP[sel][s][pair * TILE_ELEMS];
#pragma unroll
        for (int fm = 0; fm < 2; ++fm)
#pragma unroll
            for (int fn = 0; fn < 4; ++fn) {
                const int i = wm * 32 + fm * 16 + (lane >> 2);
                const int j = wn * 32 + fn * 8 + (lane & 3) * 2;
                float2 lo = {acc[fm][fn][0], acc[fm][fn][1]};
                float2 hi = {acc[fm][fn][2], acc[fm][fn][3]};
                *(float2*)&outp[i * 128 + j] = lo;
                *(float2*)&outp[(i + 8) * 128 + j] = hi;
            }
    }

    grid_sync();

    // ========== Phase 2: cross reduction (all 296 blocks) + fused final =====
    {
        float v = 0.f;
        const int t = bid * TPB_CROSS + tid;   // 42 contiguous float4 tasks/block
        if (tid < TPB_CROSS && t < CROSS_TASKS) {
            const int pair = t >> 12;
            const float w = (pair == 1) ? 2.f : 1.f;
            float4 ga = {0.f, 0.f, 0.f, 0.f}, gb = {0.f, 0.f, 0.f, 0.f};
#pragma unroll 8
            for (int s = 0; s < SPLITS; ++s) {
                const float4 a = *(const float4*)&g_GP[0][s][t * 4];
                const float4 bb = *(const float4*)&g_GP[1][s][t * 4];
                ga.x += a.x; ga.y += a.y; ga.z += a.z; ga.w += a.w;
                gb.x += bb.x; gb.y += bb.y; gb.z += bb.z; gb.w += bb.w;
            }
            v = w * (ga.x * gb.x + ga.y * gb.y + ga.z * gb.z + ga.w * gb.w);
        }
        __syncthreads();
        s_red[tid] = v;
        __syncthreads();
#pragma unroll
        for (int off = 32; off > 0; off >>= 1) {   // data only in tids 0..41 (<64)
            if (tid < off) s_red[tid] += s_red[tid + off];
            __syncthreads();
        }
        if (tid == 0) {
            g_red[bid] = s_red[0];
            __threadfence();
            s_last = (atomicAdd(&g_fin, 1u) == NBLK - 1) ? 1u : 0u;
        }
        __syncthreads();

        if (s_last) {
            __threadfence();
            float v2 = 0.f;
            if (tid < NBLK) v2 = (*(volatile float*)&g_red[tid]) * (LAMBDA / (256.f * 256.f));
            if (tid < NSTATS) v2 += *(volatile float*)&g_diag[tid];
            s_red[tid] = v2;
            __syncthreads();
#pragma unroll
            for (int off = 256; off > 0; off >>= 1) {   // data in tids 0..295 (<512)
                if (tid < off) s_red[tid] += s_red[tid + off];
                __syncthreads();
            }
            if (tid == 0) {
                out[0] = s_red[0];
                g_fin = 0;   // reset for next graph replay
            }
        }
    }
}

// ---------------------------------------------------------------------------
extern "C" void kernel_launch(void* const* d_in, const int* in_sizes, int n_in,
                              void* d_out, int out_size) {
    const float* za = (const float*)d_in[0];
    const float* zb = (const float*)d_in[1];
    float* out = (float*)d_out;
    cudaFuncSetAttribute(fused_kernel, cudaFuncAttributeMaxDynamicSharedMemorySize, DYN_SMEM);
    fused_kernel<<<NBLK, NTHR, DYN_SMEM>>>(za, zb, out);
}

// round 14
// speedup vs baseline: 1.2025x; 1.2025x over previous
#include <cuda_runtime.h>
#include <cuda_bf16.h>

#define N_ROWS 256
#define D_COLS 8192
#define LAMBDA 0.005f
#define SPLITS 24
#define NTILES 3              // symmetric 128x128 tile pairs: (0,0),(0,1),(1,1)
#define TILE_ELEMS 16384
#define BK 64                 // k per mainloop iter
#define LDB 72                // smem row stride in bf16 (144 B, odd granule count -> conflict-free)
#define TILE_BUF 18432        // 128 * 144 B, one side one stage
#define NSTAGE 3
#define A_REGION (NSTAGE * TILE_BUF)      // 55296
#define DYN_SMEM (2 * NSTAGE * TILE_BUF)  // 110592
#define NBLK 148
#define NTHR 512
#define CROSS_TASKS 12288     // 3*TILE_ELEMS/4 float4 tasks
#define NCROSSBLK 96          // 96 blocks x 128 tasks = 12288
#define SGRP 4                // split groups (6 splits each)
#define CR_STRIDE 36          // smem floats per task slot (16B-aligned, bank-spread)

// ---- scratch ----
__device__ __align__(16) __nv_bfloat16 g_Zn[2][N_ROWS * D_COLS];      // normalized bf16, 8 MB
__device__ float g_diag[128];
__device__ __align__(16) float g_GP[2][SPLITS][NTILES * TILE_ELEMS];  // 9.4 MB partials
__device__ float g_red[NBLK];
__device__ unsigned g_bar_count;
__device__ unsigned g_bar_gen;
__device__ unsigned g_fin;

// ---------------------------------------------------------------------------
__device__ __forceinline__ void grid_sync() {
    __syncthreads();
    if (threadIdx.x == 0) {
        __threadfence();
        const unsigned gen = *(volatile unsigned*)&g_bar_gen;
        if (atomicAdd(&g_bar_count, 1u) == NBLK - 1) {
            g_bar_count = 0;
            __threadfence();
            *(volatile unsigned*)&g_bar_gen = gen + 1;
        } else {
            while (*(volatile unsigned*)&g_bar_gen == gen) {}
        }
        __threadfence();
    }
    __syncthreads();
}

__device__ __forceinline__ void mma_bf16(float* c, const unsigned* a, unsigned b0, unsigned b1) {
    asm volatile(
        "mma.sync.aligned.m16n8k16.row.col.f32.bf16.bf16.f32 "
        "{%0,%1,%2,%3}, {%4,%5,%6,%7}, {%8,%9}, {%0,%1,%2,%3};\n"
        : "+f"(c[0]), "+f"(c[1]), "+f"(c[2]), "+f"(c[3])
        : "r"(a[0]), "r"(a[1]), "r"(a[2]), "r"(a[3]), "r"(b0), "r"(b1));
}
__device__ __forceinline__ void ldm4(unsigned* r, unsigned addr) {
    asm volatile("ldmatrix.sync.aligned.m8n8.x4.shared.b16 {%0,%1,%2,%3}, [%4];\n"
        : "=r"(r[0]), "=r"(r[1]), "=r"(r[2]), "=r"(r[3]) : "r"(addr));
}
__device__ __forceinline__ void cp_async16(unsigned dst, const void* src) {
    asm volatile("cp.async.cg.shared.global [%0], [%1], 16;\n" :: "r"(dst), "l"(src));
}

__global__ __launch_bounds__(NTHR, 1)
void fused_kernel(const float* __restrict__ za, const float* __restrict__ zb,
                  float* __restrict__ out) {
    extern __shared__ __align__(16) unsigned char dyn[];
    __shared__ float s_red[NTHR];
    __shared__ unsigned s_last;

    const int bid = blockIdx.x;
    const int tid = threadIdx.x;

    // ========== Phase 0 (bid<128): stats + diag + normalize =================
    if (bid < 128) {
        float (*s_st)[64 * 5] = (float (*)[64 * 5])dyn;                   // [8][320]
        float* s_mu = (float*)(dyn + 10240);                               // [2][64]
        float* s_inv = (float*)(dyn + 10240 + 512);                        // [2][64]

        const int c = tid & 63;
        const int gq = tid >> 6;          // 0..7, 32 rows each
        const int col = bid * 64 + c;
        const float* __restrict__ pa = za + (size_t)(gq * 32) * D_COLS + col;
        const float* __restrict__ pb = zb + (size_t)(gq * 32) * D_COLS + col;
        float sa = 0.f, sb = 0.f, saa = 0.f, sbb = 0.f, sab = 0.f;
#pragma unroll 8
        for (int n = 0; n < 32; ++n) {
            float a = pa[n * D_COLS];
            float b = pb[n * D_COLS];
            sa += a; sb += b;
            saa += a * a; sbb += b * b; sab += a * b;
        }
        s_st[gq][c * 5 + 0] = sa;
        s_st[gq][c * 5 + 1] = sb;
        s_st[gq][c * 5 + 2] = saa;
        s_st[gq][c * 5 + 3] = sbb;
        s_st[gq][c * 5 + 4] = sab;
        __syncthreads();

        float term = 0.f;
        if (tid < 64) {
            float t0 = 0.f, t1 = 0.f, t2 = 0.f, t3 = 0.f, t4 = 0.f;
#pragma unroll
            for (int g = 0; g < 8; ++g) {
                t0 += s_st[g][tid * 5 + 0];
                t1 += s_st[g][tid * 5 + 1];
                t2 += s_st[g][tid * 5 + 2];
                t3 += s_st[g][tid * 5 + 3];
                t4 += s_st[g][tid * 5 + 4];
            }
            const float mua = t0 * (1.f / 256.f);
            const float mub = t1 * (1.f / 256.f);
            const float ia = rsqrtf((t2 - t0 * mua) * (1.f / 255.f));
            const float ib = rsqrtf((t3 - t1 * mub) * (1.f / 255.f));
            const float cdd = (t4 - 256.f * mua * mub) * ia * ib * (1.f / 256.f);
            term = (cdd - 1.f) * (cdd - 1.f) - LAMBDA * cdd * cdd;
            s_mu[tid] = mua; s_mu[64 + tid] = mub;
            s_inv[tid] = ia; s_inv[64 + tid] = ib;
        }
        s_red[tid] = term;
        __syncthreads();
#pragma unroll
        for (int off = 32; off > 0; off >>= 1) {   // data only in tids 0..63
            if (tid < off) s_red[tid] += s_red[tid + off];
            __syncthreads();
        }
        if (tid == 0) g_diag[bid] = s_red[0];

        // normalize slab -> bf16 (L2-hot re-read). 16 row-groups x 32 col-pairs.
        const int cp2 = tid & 31;
        const int rg = tid >> 5;              // 0..15, 16 rows each
        const int lc = cp2 * 2;
        const int gcol = bid * 64 + lc;
        const float ma0 = s_mu[lc],       ma1 = s_mu[lc + 1];
        const float wa0 = s_inv[lc],      wa1 = s_inv[lc + 1];
        const float mb0 = s_mu[64 + lc],  mb1 = s_mu[64 + lc + 1];
        const float wb0 = s_inv[64 + lc], wb1 = s_inv[64 + lc + 1];
        const float* __restrict__ qa = za + (size_t)(rg * 16) * D_COLS + gcol;
        const float* __restrict__ qb = zb + (size_t)(rg * 16) * D_COLS + gcol;
        __nv_bfloat16* __restrict__ oa = g_Zn[0] + (size_t)(rg * 16) * D_COLS + gcol;
        __nv_bfloat16* __restrict__ ob = g_Zn[1] + (size_t)(rg * 16) * D_COLS + gcol;
#pragma unroll 4
        for (int n = 0; n < 16; ++n) {
            float2 va = *(const float2*)&qa[n * D_COLS];
            float2 vb = *(const float2*)&qb[n * D_COLS];
            *(__nv_bfloat162*)&oa[n * D_COLS] =
                __floats2bfloat162_rn((va.x - ma0) * wa0, (va.y - ma1) * wa1);
            *(__nv_bfloat162*)&ob[n * D_COLS] =
                __floats2bfloat162_rn((vb.x - mb0) * wb0, (vb.y - mb1) * wb1);
        }
    }

    grid_sync();

    // ========== Phase 1 (bid<144): 3-stage pipelined tensor-core Gram =======
    // 16 warps, 4x4 warp grid, 32x32 warp tiles, BK=64, 1 barrier per iter.
    if (bid < 2 * NTILES * SPLITS) {
        const int sel = bid / (NTILES * SPLITS);
        const int rem = bid % (NTILES * SPLITS);
        const int pair = rem / SPLITS;
        const int s = rem % SPLITS;
        const bool dup = (pair != 1);      // diagonal tile pairs: B tile == A tile

        const int m0 = (pair == 2) ? 128 : 0;
        const int n0 = (pair == 0) ? 0 : 128;
        // 128 k-chunks of 64: splits 0..15 get 5, 16..23 get 6
        const int ks = (s < 16) ? s * 5 : 80 + (s - 16) * 6;
        const int kn = (s < 16) ? 5 : 6;

        const __nv_bfloat16* __restrict__ gA = g_Zn[sel] + (size_t)m0 * D_COLS;
        const __nv_bfloat16* __restrict__ gB = g_Zn[sel] + (size_t)n0 * D_COLS;

        const int warp = tid >> 5;
        const int lane = tid & 31;
        const int wm = warp & 3;    // 4 m-strips of 32
        const int wn = warp >> 2;   // 4 n-strips of 32

        float acc[2][4][4];
#pragma unroll
        for (int i = 0; i < 2; ++i)
#pragma unroll
            for (int j = 0; j < 4; ++j)
#pragma unroll
                for (int k = 0; k < 4; ++k) acc[i][j][k] = 0.f;

        const unsigned sBase = (unsigned)__cvta_generic_to_shared(dyn);
        const unsigned bRegion = dup ? sBase : (sBase + (unsigned)A_REGION);
        const int laR = (lane & 7) + (lane & 8);
        const int laC = (lane >> 1) & 8;
        const int lbR = (lane & 7) + ((lane >> 1) & 8);
        const int lbC = (lane & 8);
        const unsigned aAddr = sBase + (unsigned)(((wm * 32 + laR) * LDB + laC) * 2);
        const unsigned bAddr = bRegion + (unsigned)(((wn * 32 + lbR) * LDB + lbC) * 2);

        // stage one 128x64 bf16 tile per side: 1024 16B chunks -> 2 per thread
#define STAGE(slot, kidx)                                                         \
        {                                                                         \
            const int k0_ = (ks + (kidx)) * BK;                                   \
            const unsigned so_ = (unsigned)(slot) * TILE_BUF;                     \
            _Pragma("unroll")                                                     \
            for (int i_ = 0; i_ < 2; ++i_) {                                      \
                const int l_ = i_ * NTHR + tid;                                   \
                const int r_ = l_ >> 3;                                           \
                const int c_ = l_ & 7;                                            \
                cp_async16(sBase + so_ + (unsigned)(r_ * 144 + c_ * 16),          \
                           gA + (size_t)r_ * D_COLS + k0_ + c_ * 8);              \
                if (!dup)                                                         \
                    cp_async16(sBase + (unsigned)A_REGION + so_ + (unsigned)(r_ * 144 + c_ * 16), \
                               gB + (size_t)r_ * D_COLS + k0_ + c_ * 8);          \
            }                                                                     \
            asm volatile("cp.async.commit_group;\n");                             \
        }

        STAGE(0, 0);
        STAGE(1, 1);
        for (int it = 0; it < kn; ++it) {
            if (it == kn - 1) { asm volatile("cp.async.wait_group 0;\n"); }
            else              { asm volatile("cp.async.wait_group 1;\n"); }
            __syncthreads();   // single barrier per iter: orders prev reads + this chunk's data
            if (it + 2 < kn) STAGE((it + 2) % NSTAGE, it + 2);

            const unsigned off = (unsigned)((it % NSTAGE) * TILE_BUF);
#pragma unroll
            for (int kf = 0; kf < 4; ++kf) {
                unsigned A0[4], A1[4];
                ldm4(A0, aAddr + off + (unsigned)(kf * 32));
                ldm4(A1, aAddr + off + (unsigned)(16 * LDB * 2 + kf * 32));
#pragma unroll
                for (int fp = 0; fp < 2; ++fp) {
                    unsigned B[4];
                    ldm4(B, bAddr + off + (unsigned)(fp * 16 * LDB * 2 + kf * 32));
                    mma_bf16(acc[0][2 * fp],     A0, B[0], B[1]);
                    mma_bf16(acc[0][2 * fp + 1], A0, B[2], B[3]);
                    mma_bf16(acc[1][2 * fp],     A1, B[0], B[1]);
                    mma_bf16(acc[1][2 * fp + 1], A1, B[2], B[3]);
                }
            }
        }
#undef STAGE

        float* __restrict__ outp = &g_GP[sel][s][pair * TILE_ELEMS];
#pragma unroll
        for (int fm = 0; fm < 2; ++fm)
#pragma unroll
            for (int fn = 0; fn < 4; ++fn) {
                const int i = wm * 32 + fm * 16 + (lane >> 2);
                const int j = wn * 32 + fn * 8 + (lane & 3) * 2;
                float2 lo = {acc[fm][fn][0], acc[fm][fn][1]};
                float2 hi = {acc[fm][fn][2], acc[fm][fn][3]};
                *(float2*)&outp[i * 128 + j] = lo;
                *(float2*)&outp[(i + 8) * 128 + j] = hi;
            }
    }

    grid_sync();

    // ========== Phase 2: cross reduction, split-group parallel + fused final =
    // 96 blocks x 512 threads: tid = grp*128 + task_local; each thread sums 6
    // splits of (ga, gb) for one float4 task; groups combine via smem BEFORE
    // the ga*gb product (fixed group order -> deterministic).
    {
        float v = 0.f;
        if (bid < NCROSSBLK) {
            const int tl = tid & 127;
            const int grp = tid >> 7;                 // 0..3, 6 splits each
            const int t = bid * 128 + tl;             // float4 task 0..12287
            float4 ga = {0.f, 0.f, 0.f, 0.f}, gb = {0.f, 0.f, 0.f, 0.f};
#pragma unroll
            for (int q = 0; q < 6; ++q) {
                const int s = grp * 6 + q;
                const float4 a = *(const float4*)&g_GP[0][s][t * 4];
                const float4 bb = *(const float4*)&g_GP[1][s][t * 4];
                ga.x += a.x; ga.y += a.y; ga.z += a.z; ga.w += a.w;
                gb.x += bb.x; gb.y += bb.y; gb.z += bb.z; gb.w += bb.w;
            }
            // combine groups in smem (dyn is free after gram's grid_sync)
            float* sm = (float*)dyn;                  // [128][CR_STRIDE]
            *(float4*)&sm[tl * CR_STRIDE + grp * 8 + 0] = ga;
            *(float4*)&sm[tl * CR_STRIDE + grp * 8 + 4] = gb;
            __syncthreads();
            if (grp == 0) {
                float4 GA = {0.f, 0.f, 0.f, 0.f}, GB = {0.f, 0.f, 0.f, 0.f};
#pragma unroll
                for (int g = 0; g < SGRP; ++g) {
                    const float4 a = *(const float4*)&sm[tl * CR_STRIDE + g * 8 + 0];
                    const float4 b = *(const float4*)&sm[tl * CR_STRIDE + g * 8 + 4];
                    GA.x += a.x; GA.y += a.y; GA.z += a.z; GA.w += a.w;
                    GB.x += b.x; GB.y += b.y; GB.z += b.z; GB.w += b.w;
                }
                const float w = ((t >> 12) == 1) ? 2.f : 1.f;
                v = w * (GA.x * GB.x + GA.y * GB.y + GA.z * GB.z + GA.w * GB.w);
            }
        } else {
            __syncthreads();   // keep barrier counts uniform isn't needed across blocks; local only
        }
        __syncthreads();
        s_red[tid] = v;        // nonzero only for grp==0 threads of cross blocks
        __syncthreads();
#pragma unroll
        for (int off = 64; off > 0; off >>= 1) {   // data only in tids 0..127
            if (tid < off) s_red[tid] += s_red[tid + off];
            __syncthreads();
        }
        if (tid == 0) {
            g_red[bid] = s_red[0];
            __threadfence();
            s_last = (atomicAdd(&g_fin, 1u) == NBLK - 1) ? 1u : 0u;
        }
        __syncthreads();

        if (s_last) {
            __threadfence();
            float v2 = 0.f;
            if (tid < NBLK) v2 = (*(volatile float*)&g_red[tid]) * (LAMBDA / (256.f * 256.f));
            if (tid < 128) v2 += *(volatile float*)&g_diag[tid];
            s_red[tid] = v2;
            __syncthreads();
#pragma unroll
            for (int off = 128; off > 0; off >>= 1) {   // data in tids 0..147 (<256)
                if (tid < off) s_red[tid] += s_red[tid + off];
                __syncthreads();
            }
            if (tid == 0) {
                out[0] = s_red[0];
                g_fin = 0;   // reset for next graph replay
            }
        }
    }
}

// ---------------------------------------------------------------------------
extern "C" void kernel_launch(void* const* d_in, const int* in_sizes, int n_in,
                              void* d_out, int out_size) {
    const float* za = (const float*)d_in[0];
    const float* zb = (const float*)d_in[1];
    float* out = (float*)d_out;
    cudaFuncSetAttribute(fused_kernel, cudaFuncAttributeMaxDynamicSharedMemorySize, DYN_SMEM);
    fused_kernel<<<NBLK, NTHR, DYN_SMEM>>>(za, zb, out);
}

// round 15
// speedup vs baseline: 1.2298x; 1.0227x over previous
#include <cuda_runtime.h>
#include <cuda_bf16.h>

#define N_ROWS 256
#define D_COLS 8192
#define LAMBDA 0.005f
#define SPLITS 24
#define NTILES 3              // symmetric 128x128 tile pairs: (0,0),(0,1),(1,1)
#define TILE_ELEMS 16384
#define BK 64                 // k per mainloop iter
#define LDB 72                // smem row stride in bf16 (144 B, odd granule count -> conflict-free)
#define TILE_BUF 18432        // 128 * 144 B, one side one stage
#define NSTAGE 3
#define A_REGION (NSTAGE * TILE_BUF)      // 55296
#define DYN_SMEM (2 * NSTAGE * TILE_BUF)  // 110592
#define NBLK 148
#define NTHR 512
#define CROSS_TASKS 12288     // 3*TILE_ELEMS/4 float4 tasks
#define NCROSSBLK 96          // 96 blocks x 128 tasks = 12288
#define SGRP 4                // split groups (6 splits each)
#define CR_STRIDE 36          // smem floats per task slot

// ---- scratch ----
__device__ __align__(16) __nv_bfloat16 g_Zn[2][N_ROWS * D_COLS];      // normalized bf16, 8 MB
__device__ float g_diag[128];
__device__ __align__(16) float g_GP[2][SPLITS][NTILES * TILE_ELEMS];  // 9.4 MB partials
__device__ float g_red[NBLK];
__device__ unsigned g_bar_count;
__device__ unsigned g_bar_gen;
__device__ unsigned g_fin;

// ---------------------------------------------------------------------------
__device__ __forceinline__ void grid_sync() {
    __syncthreads();
    if (threadIdx.x == 0) {
        __threadfence();
        const unsigned gen = *(volatile unsigned*)&g_bar_gen;
        if (atomicAdd(&g_bar_count, 1u) == NBLK - 1) {
            g_bar_count = 0;
            __threadfence();
            *(volatile unsigned*)&g_bar_gen = gen + 1;
        } else {
            while (*(volatile unsigned*)&g_bar_gen == gen) {}
        }
        __threadfence();
    }
    __syncthreads();
}

__device__ __forceinline__ void mma_bf16(float* c, const unsigned* a, unsigned b0, unsigned b1) {
    asm volatile(
        "mma.sync.aligned.m16n8k16.row.col.f32.bf16.bf16.f32 "
        "{%0,%1,%2,%3}, {%4,%5,%6,%7}, {%8,%9}, {%0,%1,%2,%3};\n"
        : "+f"(c[0]), "+f"(c[1]), "+f"(c[2]), "+f"(c[3])
        : "r"(a[0]), "r"(a[1]), "r"(a[2]), "r"(a[3]), "r"(b0), "r"(b1));
}
__device__ __forceinline__ void ldm4(unsigned* r, unsigned addr) {
    asm volatile("ldmatrix.sync.aligned.m8n8.x4.shared.b16 {%0,%1,%2,%3}, [%4];\n"
        : "=r"(r[0]), "=r"(r[1]), "=r"(r[2]), "=r"(r[3]) : "r"(addr));
}
__device__ __forceinline__ void cp_async16(unsigned dst, const void* src) {
    asm volatile("cp.async.cg.shared.global [%0], [%1], 16;\n" :: "r"(dst), "l"(src));
}

__global__ __launch_bounds__(NTHR, 1)
void fused_kernel(const float* __restrict__ za, const float* __restrict__ zb,
                  float* __restrict__ out) {
    extern __shared__ __align__(16) unsigned char dyn[];
    __shared__ float s_red[NTHR];
    __shared__ unsigned s_last;

    const int bid = blockIdx.x;
    const int tid = threadIdx.x;

    // ========== Phase 0 (bid<128): single-pass float4 stats+normalize+diag ==
    if (bid < 128) {
        // smem: partials [32 rg][16 cq][5 float4] = 40960 B; mu/inv after
        float* s_stf = (float*)dyn;
        float* s_mu = (float*)(dyn + 40960);                               // [2][64]
        float* s_inv = (float*)(dyn + 40960 + 512);                        // [2][64]

        const int cq = tid & 15;          // column quad (4 cols)
        const int rg = tid >> 4;          // 0..31, 8 rows each
        const int col0 = bid * 64 + cq * 4;
        const float* __restrict__ pa = za + (size_t)(rg * 8) * D_COLS + col0;
        const float* __restrict__ pb = zb + (size_t)(rg * 8) * D_COLS + col0;

        float4 va[8], vb[8];
#pragma unroll
        for (int n = 0; n < 8; ++n) {
            va[n] = *(const float4*)&pa[n * D_COLS];
            vb[n] = *(const float4*)&pb[n * D_COLS];
        }
        float4 sa = {0,0,0,0}, sb = {0,0,0,0}, saa = {0,0,0,0}, sbb = {0,0,0,0}, sab = {0,0,0,0};
#pragma unroll
        for (int n = 0; n < 8; ++n) {
            sa.x += va[n].x; sa.y += va[n].y; sa.z += va[n].z; sa.w += va[n].w;
            sb.x += vb[n].x; sb.y += vb[n].y; sb.z += vb[n].z; sb.w += vb[n].w;
            saa.x += va[n].x * va[n].x; saa.y += va[n].y * va[n].y;
            saa.z += va[n].z * va[n].z; saa.w += va[n].w * va[n].w;
            sbb.x += vb[n].x * vb[n].x; sbb.y += vb[n].y * vb[n].y;
            sbb.z += vb[n].z * vb[n].z; sbb.w += vb[n].w * vb[n].w;
            sab.x += va[n].x * vb[n].x; sab.y += va[n].y * vb[n].y;
            sab.z += va[n].z * vb[n].z; sab.w += va[n].w * vb[n].w;
        }
        {
            float* p = &s_stf[(rg * 16 + cq) * 20];
            *(float4*)&p[0] = sa;  *(float4*)&p[4] = sb;
            *(float4*)&p[8] = saa; *(float4*)&p[12] = sbb; *(float4*)&p[16] = sab;
        }
        __syncthreads();

        float term = 0.f;
        if (tid < 64) {
            const int c = tid;
            const int q = c >> 2, j = c & 3;
            float t0 = 0.f, t1 = 0.f, t2 = 0.f, t3 = 0.f, t4 = 0.f;
#pragma unroll 8
            for (int g = 0; g < 32; ++g) {
                const float* p = &s_stf[(g * 16 + q) * 20];
                t0 += p[j]; t1 += p[4 + j]; t2 += p[8 + j]; t3 += p[12 + j]; t4 += p[16 + j];
            }
            const float mua = t0 * (1.f / 256.f);
            const float mub = t1 * (1.f / 256.f);
            const float ia = rsqrtf((t2 - t0 * mua) * (1.f / 255.f));
            const float ib = rsqrtf((t3 - t1 * mub) * (1.f / 255.f));
            const float cdd = (t4 - 256.f * mua * mub) * ia * ib * (1.f / 256.f);
            term = (cdd - 1.f) * (cdd - 1.f) - LAMBDA * cdd * cdd;
            s_mu[c] = mua; s_mu[64 + c] = mub;
            s_inv[c] = ia; s_inv[64 + c] = ib;
        }
        s_red[tid] = term;
        __syncthreads();
#pragma unroll
        for (int off = 32; off > 0; off >>= 1) {   // data only in tids 0..63
            if (tid < off) s_red[tid] += s_red[tid + off];
            __syncthreads();
        }
        if (tid == 0) g_diag[bid] = s_red[0];

        // normalize from registers, write bf16 (4 cols = uint2 per row)
        const float4 ma = *(const float4*)&s_mu[cq * 4];
        const float4 wa = *(const float4*)&s_inv[cq * 4];
        const float4 mb = *(const float4*)&s_mu[64 + cq * 4];
        const float4 wb = *(const float4*)&s_inv[64 + cq * 4];
        __nv_bfloat16* __restrict__ oa = g_Zn[0] + (size_t)(rg * 8) * D_COLS + col0;
        __nv_bfloat16* __restrict__ ob = g_Zn[1] + (size_t)(rg * 8) * D_COLS + col0;
#pragma unroll
        for (int n = 0; n < 8; ++n) {
            union { __nv_bfloat162 h2[2]; uint2 u; } ua, ub;
            ua.h2[0] = __floats2bfloat162_rn((va[n].x - ma.x) * wa.x, (va[n].y - ma.y) * wa.y);
            ua.h2[1] = __floats2bfloat162_rn((va[n].z - ma.z) * wa.z, (va[n].w - ma.w) * wa.w);
            ub.h2[0] = __floats2bfloat162_rn((vb[n].x - mb.x) * wb.x, (vb[n].y - mb.y) * wb.y);
            ub.h2[1] = __floats2bfloat162_rn((vb[n].z - mb.z) * wb.z, (vb[n].w - mb.w) * wb.w);
            *(uint2*)&oa[n * D_COLS] = ua.u;
            *(uint2*)&ob[n * D_COLS] = ub.u;
        }
    }

    grid_sync();

    // ========== Phase 1 (bid<144): 3-stage pipelined tensor-core Gram =======
    // 16 warps, 4x4 warp grid, 32x32 warp tiles, BK=64, 1 barrier per iter.
    if (bid < 2 * NTILES * SPLITS) {
        const int sel = bid / (NTILES * SPLITS);
        const int rem = bid % (NTILES * SPLITS);
        const int pair = rem / SPLITS;
        const int s = rem % SPLITS;
        const bool dup = (pair != 1);      // diagonal tile pairs: B tile == A tile

        const int m0 = (pair == 2) ? 128 : 0;
        const int n0 = (pair == 0) ? 0 : 128;
        // 128 k-chunks of 64: splits 0..15 get 5, 16..23 get 6
        const int ks = (s < 16) ? s * 5 : 80 + (s - 16) * 6;
        const int kn = (s < 16) ? 5 : 6;

        const __nv_bfloat16* __restrict__ gA = g_Zn[sel] + (size_t)m0 * D_COLS;
        const __nv_bfloat16* __restrict__ gB = g_Zn[sel] + (size_t)n0 * D_COLS;

        const int warp = tid >> 5;
        const int lane = tid & 31;
        const int wm = warp & 3;    // 4 m-strips of 32
        const int wn = warp >> 2;   // 4 n-strips of 32

        float acc[2][4][4];
#pragma unroll
        for (int i = 0; i < 2; ++i)
#pragma unroll
            for (int j = 0; j < 4; ++j)
#pragma unroll
                for (int k = 0; k < 4; ++k) acc[i][j][k] = 0.f;

        const unsigned sBase = (unsigned)__cvta_generic_to_shared(dyn);
        const unsigned bRegion = dup ? sBase : (sBase + (unsigned)A_REGION);
        const int laR = (lane & 7) + (lane & 8);
        const int laC = (lane >> 1) & 8;
        const int lbR = (lane & 7) + ((lane >> 1) & 8);
        const int lbC = (lane & 8);
        const unsigned aAddr = sBase + (unsigned)(((wm * 32 + laR) * LDB + laC) * 2);
        const unsigned bAddr = bRegion + (unsigned)(((wn * 32 + lbR) * LDB + lbC) * 2);

        // stage one 128x64 bf16 tile per side: 1024 16B chunks -> 2 per thread
#define STAGE(slot, kidx)                                                         \
        {                                                                         \
            const int k0_ = (ks + (kidx)) * BK;                                   \
            const unsigned so_ = (unsigned)(slot) * TILE_BUF;                     \
            _Pragma("unroll")                                                     \
            for (int i_ = 0; i_ < 2; ++i_) {                                      \
                const int l_ = i_ * NTHR + tid;                                   \
                const int r_ = l_ >> 3;                                           \
                const int c_ = l_ & 7;                                            \
                cp_async16(sBase + so_ + (unsigned)(r_ * 144 + c_ * 16),          \
                           gA + (size_t)r_ * D_COLS + k0_ + c_ * 8);              \
                if (!dup)                                                         \
                    cp_async16(sBase + (unsigned)A_REGION + so_ + (unsigned)(r_ * 144 + c_ * 16), \
                               gB + (size_t)r_ * D_COLS + k0_ + c_ * 8);          \
            }                                                                     \
            asm volatile("cp.async.commit_group;\n");                             \
        }

        STAGE(0, 0);
        STAGE(1, 1);
        for (int it = 0; it < kn; ++it) {
            if (it == kn - 1) { asm volatile("cp.async.wait_group 0;\n"); }
            else              { asm volatile("cp.async.wait_group 1;\n"); }
            __syncthreads();   // single barrier per iter: orders prev reads + this chunk's data
            if (it + 2 < kn) STAGE((it + 2) % NSTAGE, it + 2);

            const unsigned off = (unsigned)((it % NSTAGE) * TILE_BUF);
#pragma unroll
            for (int kf = 0; kf < 4; ++kf) {
                unsigned A0[4], A1[4];
                ldm4(A0, aAddr + off + (unsigned)(kf * 32));
                ldm4(A1, aAddr + off + (unsigned)(16 * LDB * 2 + kf * 32));
#pragma unroll
                for (int fp = 0; fp < 2; ++fp) {
                    unsigned B[4];
                    ldm4(B, bAddr + off + (unsigned)(fp * 16 * LDB * 2 + kf * 32));
                    mma_bf16(acc[0][2 * fp],     A0, B[0], B[1]);
                    mma_bf16(acc[0][2 * fp + 1], A0, B[2], B[3]);
                    mma_bf16(acc[1][2 * fp],     A1, B[0], B[1]);
                    mma_bf16(acc[1][2 * fp + 1], A1, B[2], B[3]);
                }
            }
        }
#undef STAGE

        float* __restrict__ outp = &g_GP[sel][s][pair * TILE_ELEMS];
#pragma unroll
        for (int fm = 0; fm < 2; ++fm)
#pragma unroll
            for (int fn = 0; fn < 4; ++fn) {
                const int i = wm * 32 + fm * 16 + (lane >> 2);
                const int j = wn * 32 + fn * 8 + (lane & 3) * 2;
                float2 lo = {acc[fm][fn][0], acc[fm][fn][1]};
                float2 hi = {acc[fm][fn][2], acc[fm][fn][3]};
                *(float2*)&outp[i * 128 + j] = lo;
                *(float2*)&outp[(i + 8) * 128 + j] = hi;
            }
    }

    grid_sync();

    // ========== Phase 2: cross reduction, split-group parallel + fused final =
    {
        float v = 0.f;
        if (bid < NCROSSBLK) {
            const int tl = tid & 127;
            const int grp = tid >> 7;                 // 0..3, 6 splits each
            const int t = bid * 128 + tl;             // float4 task 0..12287
            float4 ga = {0.f, 0.f, 0.f, 0.f}, gb = {0.f, 0.f, 0.f, 0.f};
#pragma unroll
            for (int q = 0; q < 6; ++q) {
                const int s = grp * 6 + q;
                const float4 a = *(const float4*)&g_GP[0][s][t * 4];
                const float4 bb = *(const float4*)&g_GP[1][s][t * 4];
                ga.x += a.x; ga.y += a.y; ga.z += a.z; ga.w += a.w;
                gb.x += bb.x; gb.y += bb.y; gb.z += bb.z; gb.w += bb.w;
            }
            float* sm = (float*)dyn;                  // [128][CR_STRIDE]
            *(float4*)&sm[tl * CR_STRIDE + grp * 8 + 0] = ga;
            *(float4*)&sm[tl * CR_STRIDE + grp * 8 + 4] = gb;
            __syncthreads();
            if (grp == 0) {
                float4 GA = {0.f, 0.f, 0.f, 0.f}, GB = {0.f, 0.f, 0.f, 0.f};
#pragma unroll
                for (int g = 0; g < SGRP; ++g) {
                    const float4 a = *(const float4*)&sm[tl * CR_STRIDE + g * 8 + 0];
                    const float4 b = *(const float4*)&sm[tl * CR_STRIDE + g * 8 + 4];
                    GA.x += a.x; GA.y += a.y; GA.z += a.z; GA.w += a.w;
                    GB.x += b.x; GB.y += b.y; GB.z += b.z; GB.w += b.w;
                }
                const float w = ((t >> 12) == 1) ? 2.f : 1.f;
                v = w * (GA.x * GB.x + GA.y * GB.y + GA.z * GB.z + GA.w * GB.w);
            }
        } else {
            __syncthreads();
        }
        __syncthreads();
        s_red[tid] = v;
        __syncthreads();
#pragma unroll
        for (int off = 64; off > 0; off >>= 1) {   // data only in tids 0..127
            if (tid < off) s_red[tid] += s_red[tid + off];
            __syncthreads();
        }
        if (tid == 0) {
            g_red[bid] = s_red[0];
            __threadfence();
            s_last = (atomicAdd(&g_fin, 1u) == NBLK - 1) ? 1u : 0u;
        }
        __syncthreads();

        if (s_last) {
            __threadfence();
            float v2 = 0.f;
            if (tid < NBLK) v2 = (*(volatile float*)&g_red[tid]) * (LAMBDA / (256.f * 256.f));
            if (tid < 128) v2 += *(volatile float*)&g_diag[tid];
            s_red[tid] = v2;
            __syncthreads();
#pragma unroll
            for (int off = 128; off > 0; off >>= 1) {   // data in tids 0..147 (<256)
                if (tid < off) s_red[tid] += s_red[tid + off];
                __syncthreads();
            }
            if (tid == 0) {
                out[0] = s_red[0];
                g_fin = 0;   // reset for next graph replay
            }
        }
    }
}

// ---------------------------------------------------------------------------
extern "C" void kernel_launch(void* const* d_in, const int* in_sizes, int n_in,
                              void* d_out, int out_size) {
    const float* za = (const float*)d_in[0];
    const float* zb = (const float*)d_in[1];
    float* out = (float*)d_out;
    cudaFuncSetAttribute(fused_kernel, cudaFuncAttributeMaxDynamicSharedMemorySize, DYN_SMEM);
    fused_kernel<<<NBLK, NTHR, DYN_SMEM>>>(za, zb, out);
}